// round 1
// baseline (speedup 1.0000x reference)
#include <cuda_runtime.h>

// ---------------- sizes ----------------
#define NB 16          // batch
#define CH 64          // width
#define SS 256         // spatial
#define M0 16
#define NMODE 32       // 16 top + 16 bottom kx modes
#define PLANE (SS*SS)  // 65536
#define SZH (NB*CH*PLANE)

// ---------------- device scratch ----------------
__device__ float  g_h[2][SZH];                 // ping-pong activations (b,c,x,y)
__device__ float2 g_A [NB*CH*SS*M0];           // after y-DFT: [b][c][x][ky]
__device__ float2 g_ft[NMODE*M0*NB*CH];        // [mode][b][i]
__device__ float2 g_oft[NMODE*M0*NB*CH];       // [mode][b][o]
__device__ float2 g_t [NB*CH*SS*M0];           // [b][o][x][ky]
__device__ float2 g_W [4*NMODE*M0*CH*CH];      // [blk][mode][i][o]

// ---------------- weight re-layout (once per launch) ----------------
__global__ void k_wprep(const float2* __restrict__ w1, const float2* __restrict__ w2) {
    int idx = blockIdx.x * blockDim.x + threadIdx.x;   // 4*512*4096 = 8388608
    int o   = idx & 63;
    int i   = (idx >> 6) & 63;
    int ky  = (idx >> 12) & 15;
    int m   = (idx >> 16) & 31;
    int blk = (idx >> 21);
    const float2* src = (m < 16) ? w1 : w2;
    int mx = (m < 16) ? m : (m - 16);
    g_W[idx] = src[((((long)blk * 64 + i) * 64 + o) * 16 + mx) * 16 + ky];
}

// ---------------- lift: x(b,x,y,3) @ fc0 -> g_h[0] (b,c,x,y) ----------------
__global__ void k_lift(const float* __restrict__ x, const float* __restrict__ w0,
                       const float* __restrict__ b0) {
    __shared__ float sw[192];
    __shared__ float sb[64];
    int t = threadIdx.x;
    if (t < 192) sw[t] = w0[t];
    if (t < 64)  sb[t] = b0[t];
    __syncthreads();
    int b = blockIdx.y, xx = blockIdx.x, y = t;
    const float* xp = x + (((long)b * SS + xx) * SS + y) * 3;
    float x0 = xp[0], x1 = xp[1], x2 = xp[2];
    float* out = g_h[0] + (long)b * CH * PLANE + xx * SS + y;
#pragma unroll
    for (int c = 0; c < CH; c++)
        out[(long)c * PLANE] = x0 * sw[c] + x1 * sw[64 + c] + x2 * sw[128 + c] + sb[c];
}

// ---------------- forward DFT over y: g_h[sel] -> g_A ----------------
// A[b][c][x][ky] = (1/65536) sum_y h[..,y] * e^{-2pi i ky y/256}
__global__ void k_dfty(int sel) {
    __shared__ float sh[32 * SS];   // 32 x-rows
    int b = blockIdx.z, c = blockIdx.y, x0 = blockIdx.x * 32;
    const float* src = g_h[sel] + (long)(b * CH + c) * PLANE + (long)x0 * SS;
    for (int k = threadIdx.x; k < 32 * SS; k += 256) sh[k] = src[k];
    __syncthreads();
    int ky = threadIdx.x & 15;
    int rg = threadIdx.x >> 4;           // 16 groups x 2 rows
    float stepS, stepC;
    sincospif((float)ky / 128.0f, &stepS, &stepC);      // step angle = 2*pi*ky/256
    const float* r0 = sh + rg * 2 * SS;
    const float* r1 = r0 + SS;
    float ar0 = 0.f, ai0 = 0.f, ar1 = 0.f, ai1 = 0.f;
    for (int y0 = 0; y0 < SS; y0 += 32) {
        float s2, c2;
        sincospif((float)(ky * y0) / 128.0f, &s2, &c2);  // exact integer arg
        float tr = c2, ti = -s2;                         // e^{-i phi}
#pragma unroll
        for (int k = 0; k < 32; k++) {
            float v0 = r0[y0 + k], v1 = r1[y0 + k];
            ar0 = fmaf(v0, tr, ar0); ai0 = fmaf(v0, ti, ai0);
            ar1 = fmaf(v1, tr, ar1); ai1 = fmaf(v1, ti, ai1);
            float nr = tr * stepC + ti * stepS;          // multiply by e^{-i step}
            ti = ti * stepC - tr * stepS;
            tr = nr;
        }
    }
    const float sc = 1.0f / 65536.0f;
    long base = ((long)(b * CH + c) * SS + (x0 + rg * 2)) * M0 + ky;
    g_A[base]      = make_float2(ar0 * sc, ai0 * sc);
    g_A[base + M0] = make_float2(ar1 * sc, ai1 * sc);
}

// ---------------- forward DFT over x: g_A -> g_ft ----------------
// ft[m][ky][b][i] = sum_x A[b][i][x][ky] * e^{-2pi i kx_m x/256}
__global__ void k_dftx() {
    __shared__ float2 sh[SS * M0];
    int b = blockIdx.y, i = blockIdx.x;
    const float2* src = g_A + (long)(b * CH + i) * SS * M0;
    for (int k = threadIdx.x; k < SS * M0; k += 512) sh[k] = src[k];
    __syncthreads();
    int ky = threadIdx.x & 15;
    int m  = threadIdx.x >> 4;      // 0..31
    int kxp = (m < 16) ? m : (m - 32);
    float ang = -(float)kxp / 128.0f;                  // per-step, pi units
    float stepS, stepC;
    sincospif(ang, &stepS, &stepC);
    float ar = 0.f, ai = 0.f;
    for (int x0 = 0; x0 < SS; x0 += 32) {
        float s2, c2;
        sincospif(ang * (float)x0, &s2, &c2);
        float tr = c2, ti = s2;
#pragma unroll
        for (int k = 0; k < 32; k++) {
            float2 a = sh[(x0 + k) * M0 + ky];
            ar += a.x * tr - a.y * ti;
            ai += a.x * ti + a.y * tr;
            float nr = tr * stepC - ti * stepS;
            ti = tr * stepS + ti * stepC;
            tr = nr;
        }
    }
    g_ft[(long)(m * M0 + ky) * (NB * CH) + b * CH + i] = make_float2(ar, ai);
}

// ---------------- per-mode complex channel mix: g_ft -> g_oft ----------------
__global__ void k_mix(int blk) {
    __shared__ float2 F[NB * CH];     // [b][i]
    int mode = blockIdx.x;            // 0..511
    const float2* src = g_ft + (long)mode * (NB * CH);
    for (int k = threadIdx.x; k < NB * CH; k += 256) F[k] = src[k];
    __syncthreads();
    const float2* W = g_W + ((long)blk * (NMODE * M0) + mode) * (CH * CH);
    int o  = threadIdx.x & 63;
    int bg = threadIdx.x >> 6;        // 4 groups x 4 batches
    float accr[4] = {0.f, 0.f, 0.f, 0.f};
    float acci[4] = {0.f, 0.f, 0.f, 0.f};
    for (int i = 0; i < CH; i++) {
        float2 w = W[i * CH + o];
#pragma unroll
        for (int bb = 0; bb < 4; bb++) {
            float2 f = F[(bg * 4 + bb) * CH + i];
            accr[bb] += f.x * w.x - f.y * w.y;
            acci[bb] += f.x * w.y + f.y * w.x;
        }
    }
#pragma unroll
    for (int bb = 0; bb < 4; bb++)
        g_oft[(long)mode * (NB * CH) + (bg * 4 + bb) * CH + o] = make_float2(accr[bb], acci[bb]);
}

// ---------------- inverse DFT over x: g_oft -> g_t ----------------
// t[b][o][x][ky] = sum_m oft[m][ky][b][o] e^{+2pi i kx_m x/256}
__global__ void k_idftx() {
    __shared__ float2 so[NMODE * M0];
    int b = blockIdx.y, o = blockIdx.x;
    for (int k = threadIdx.x; k < NMODE * M0; k += 256)
        so[k] = g_oft[(long)k * (NB * CH) + b * CH + o];
    __syncthreads();
    int x = threadIdx.x;
    float accr[M0], acci[M0];
#pragma unroll
    for (int ky = 0; ky < M0; ky++) { accr[ky] = 0.f; acci[ky] = 0.f; }
    for (int m = 0; m < NMODE; m++) {
        int kxp = (m < 16) ? m : (m - 32);
        float s, c;
        sincospif((float)(kxp * x) / 128.0f, &s, &c);    // exact integer arg
#pragma unroll
        for (int ky = 0; ky < M0; ky++) {
            float2 a = so[m * M0 + ky];
            accr[ky] += a.x * c - a.y * s;
            acci[ky] += a.x * s + a.y * c;
        }
    }
    float2* dst = g_t + ((long)(b * CH + o) * SS + x) * M0;
#pragma unroll
    for (int ky = 0; ky < M0; ky++) dst[ky] = make_float2(accr[ky], acci[ky]);
}

// ---------------- block epilogue: inverse-y DFT + 1x1 conv + bias (+relu) ----------------
// dyn smem: sh_t[64*16] f2 | trig[16*128] f2 | sh_h[64*128] f | cw_s[4096] f | cb_s[64] f
#define SMEM_FINAL (1024*8 + 2048*8 + 8192*4 + 4096*4 + 64*4)
__global__ void k_final(int sel, const float* __restrict__ cw, const float* __restrict__ cb,
                        int relu) {
    extern __shared__ float smem[];
    float2* sh_t = (float2*)smem;            // 1024
    float2* trig = sh_t + 1024;              // 2048
    float*  sh_h = (float*)(trig + 2048);    // 8192
    float*  cw_s = sh_h + 8192;              // 4096
    float*  cb_s = cw_s + 4096;              // 64
    int t = threadIdx.x;                     // 128 threads
    int b = blockIdx.z, xx = blockIdx.y, yb = blockIdx.x * 128;
    const float* hin = g_h[sel];

    for (int idx = t; idx < 64 * 128; idx += 128) {
        int i = idx >> 7, yl = idx & 127;
        sh_h[idx] = hin[(long)(b * CH + i) * PLANE + xx * SS + yb + yl];
    }
    for (int idx = t; idx < 1024; idx += 128) {
        int o = idx >> 4, ky = idx & 15;
        sh_t[idx] = g_t[((long)(b * CH + o) * SS + xx) * M0 + ky];
    }
    for (int idx = t; idx < 4096; idx += 128) {
        int o = idx >> 6, i = idx & 63;
        cw_s[i * 64 + o] = cw[idx];          // transpose to [i][o]
    }
    if (t < 64) cb_s[t] = cb[t];
    for (int idx = t; idx < 2048; idx += 128) {
        int ky = idx >> 7, yl = idx & 127;
        if (ky == 0) trig[idx] = make_float2(1.f, 0.f);
        else {
            float s, c;
            sincospif((float)(ky * (yb + yl)) / 128.0f, &s, &c);
            trig[idx] = make_float2(2.f * c, -2.f * s);
        }
    }
    __syncthreads();

    int og = t >> 5;        // 4 groups of 16 output channels
    int yth = t & 31;       // strided y: y = yb + yth + 32*yy
    float acc[16][4];
#pragma unroll
    for (int oo = 0; oo < 16; oo++)
#pragma unroll
        for (int yy = 0; yy < 4; yy++) acc[oo][yy] = 0.f;

    // 1x1 conv path
    for (int i = 0; i < CH; i++) {
        float hv[4];
#pragma unroll
        for (int yy = 0; yy < 4; yy++) hv[yy] = sh_h[i * 128 + yth + 32 * yy];
#pragma unroll
        for (int oo = 0; oo < 16; oo++) {
            float w = cw_s[i * 64 + og * 16 + oo];
#pragma unroll
            for (int yy = 0; yy < 4; yy++) acc[oo][yy] += w * hv[yy];
        }
    }
    // spectral inverse-y path
    for (int ky = 0; ky < M0; ky++) {
        float2 tg[4];
#pragma unroll
        for (int yy = 0; yy < 4; yy++) tg[yy] = trig[ky * 128 + yth + 32 * yy];
#pragma unroll
        for (int oo = 0; oo < 16; oo++) {
            float2 tv = sh_t[(og * 16 + oo) * M0 + ky];
#pragma unroll
            for (int yy = 0; yy < 4; yy++)
                acc[oo][yy] += tv.x * tg[yy].x + tv.y * tg[yy].y;
        }
    }
    float* hout = g_h[sel ^ 1];
#pragma unroll
    for (int oo = 0; oo < 16; oo++) {
        int o = og * 16 + oo;
        float bias = cb_s[o];
#pragma unroll
        for (int yy = 0; yy < 4; yy++) {
            float v = acc[oo][yy] + bias;
            if (relu) v = fmaxf(v, 0.f);
            hout[(long)(b * CH + o) * PLANE + xx * SS + yb + yth + 32 * yy] = v;
        }
    }
}

// ---------------- fused fc1 + relu + fc2 ----------------
// dyn smem: sh_h[64*64] | w1s[64*256] | b1s[256] | f2s[256] | sred[64]
#define SMEM_FC ((4096 + 16384 + 256 + 256 + 64) * 4)
__global__ void k_fc(int sel, const float* __restrict__ fc1w, const float* __restrict__ fc1b,
                     const float* __restrict__ fc2w, const float* __restrict__ fc2b,
                     float* __restrict__ out) {
    extern __shared__ float smem[];
    float* sh_h = smem;              // 4096
    float* w1s  = sh_h + 4096;       // 16384
    float* b1s  = w1s + 16384;       // 256
    float* f2s  = b1s + 256;         // 256
    float* sred = f2s + 256;         // 64
    int t = threadIdx.x;             // 256 threads
    int b = blockIdx.z, xx = blockIdx.y, yb = blockIdx.x * 64;
    const float* hin = g_h[sel];

    for (int idx = t; idx < 4096; idx += 256) {
        int i = idx >> 6, yl = idx & 63;
        sh_h[idx] = hin[(long)(b * CH + i) * PLANE + xx * SS + yb + yl];
    }
    for (int idx = t; idx < 16384; idx += 256) w1s[idx] = fc1w[idx];
    if (t < 256) { b1s[t] = fc1b[t]; f2s[t] = fc2w[t]; }
    if (t < 64)  sred[t] = fc2b[0];
    __syncthreads();

    int jg = t >> 3;   // 32 groups x 8 j
    int yth = t & 7;   // y = yb + yth + 8*yy
    float acc[8][8];
#pragma unroll
    for (int jj = 0; jj < 8; jj++)
#pragma unroll
        for (int yy = 0; yy < 8; yy++) acc[jj][yy] = b1s[jg * 8 + jj];

    for (int c = 0; c < CH; c++) {
        float hv[8];
#pragma unroll
        for (int yy = 0; yy < 8; yy++) hv[yy] = sh_h[c * 64 + yth + 8 * yy];
#pragma unroll
        for (int jj = 0; jj < 8; jj++) {
            float w = w1s[c * 256 + jg * 8 + jj];
#pragma unroll
            for (int yy = 0; yy < 8; yy++) acc[jj][yy] += w * hv[yy];
        }
    }
    float p[8];
#pragma unroll
    for (int yy = 0; yy < 8; yy++) p[yy] = 0.f;
#pragma unroll
    for (int jj = 0; jj < 8; jj++) {
        float f2 = f2s[jg * 8 + jj];
#pragma unroll
        for (int yy = 0; yy < 8; yy++) p[yy] += fmaxf(acc[jj][yy], 0.f) * f2;
    }
#pragma unroll
    for (int yy = 0; yy < 8; yy++) atomicAdd(&sred[yth + 8 * yy], p[yy]);
    __syncthreads();
    if (t < 64) out[((long)b * SS + xx) * SS + yb + t] = sred[t];
}

// ---------------- launch ----------------
extern "C" void kernel_launch(void* const* d_in, const int* in_sizes, int n_in,
                              void* d_out, int out_size) {
    const float* x     = (const float*)d_in[0];
    const float* fc0w  = (const float*)d_in[1];
    const float* fc0b  = (const float*)d_in[2];
    const float2* w1   = (const float2*)d_in[3];
    const float2* w2   = (const float2*)d_in[4];
    const float* cw    = (const float*)d_in[5];
    const float* cb    = (const float*)d_in[6];
    const float* fc1w  = (const float*)d_in[7];
    const float* fc1b  = (const float*)d_in[8];
    const float* fc2w  = (const float*)d_in[9];
    const float* fc2b  = (const float*)d_in[10];
    float* out = (float*)d_out;

    cudaFuncSetAttribute(k_final, cudaFuncAttributeMaxDynamicSharedMemorySize, SMEM_FINAL);
    cudaFuncSetAttribute(k_fc,    cudaFuncAttributeMaxDynamicSharedMemorySize, SMEM_FC);

    k_wprep<<<(4 * NMODE * M0 * CH * CH) / 256, 256>>>(w1, w2);
    k_lift<<<dim3(SS, NB), 256>>>(x, fc0w, fc0b);

    int cur = 0;
    for (int blk = 0; blk < 4; blk++) {
        k_dfty<<<dim3(8, CH, NB), 256>>>(cur);
        k_dftx<<<dim3(CH, NB), 512>>>();
        k_mix<<<NMODE * M0, 256>>>(blk);
        k_idftx<<<dim3(CH, NB), 256>>>();
        k_final<<<dim3(2, SS, NB), 128, SMEM_FINAL>>>(cur, cw + (long)blk * CH * CH,
                                                      cb + blk * CH, blk < 3 ? 1 : 0);
        cur ^= 1;
    }
    k_fc<<<dim3(4, SS, NB), 256, SMEM_FC>>>(cur, fc1w, fc1b, fc2w, fc2b, out);
}